// round 1
// baseline (speedup 1.0000x reference)
#include <cuda_runtime.h>
#include <cstdint>

#define HW 512
#define LPATCH 4096

// ---------------- scratch (static device globals; no allocation) ----------------
__device__ float d_M[64 * 64];        // composed linear  M = w2 @ w1
__device__ float d_wc[3 * 81];        // composed conv kernel [c][9][9]
__device__ float d_Wr[9 * 3 * 49];    // Wr[r][c][q] = sum_m w2[m,r]*w1[m,c,q]
__device__ float d_beta[9];           // beta[r] = sum_m w2[m,r]*b1[m]
__device__ float d_bc;                // composed bias
__device__ float d_delta[4][4][512];  // border corrections [b][edge][idx]
__device__ float d_uimg[(size_t)4 * 4096 * 64];
__device__ float d_ufea[(size_t)4 * 4096 * 64];

// ---------------- k0: compose weights ----------------
__global__ void k0_compose(const float* __restrict__ w1l, const float* __restrict__ w2l,
                           const float* __restrict__ wi1, const float* __restrict__ bi1,
                           const float* __restrict__ wi2, const float* __restrict__ bi2) {
    int t = threadIdx.x;  // 256 threads, 1 block
    // M[i][j] = sum_k w2[i,k] * w1[k,j]   (w2:[64,128], w1:[128,64])
    for (int o = t; o < 64 * 64; o += 256) {
        int i = o >> 6, j = o & 63;
        float s = 0.f;
        for (int k = 0; k < 128; k++) s += w2l[i * 128 + k] * w1l[k * 64 + j];
        d_M[o] = s;
    }
    // wc[c][sy][sx] = sum_m sum_{r} w2[m,ry,rx] * w1[m,c,sy-ry,sx-rx]
    for (int o = t; o < 3 * 81; o += 256) {
        int c = o / 81, s = o % 81, sy = s / 9, sx = s % 9;
        float acc = 0.f;
        for (int ry = 0; ry < 3; ry++)
            for (int rx = 0; rx < 3; rx++) {
                int qy = sy - ry, qx = sx - rx;
                if (qy < 0 || qy > 6 || qx < 0 || qx > 6) continue;
                for (int m = 0; m < 64; m++)
                    acc += wi2[m * 9 + ry * 3 + rx] * wi1[(m * 3 + c) * 49 + qy * 7 + qx];
            }
        d_wc[o] = acc;
    }
    // Wr[r][c][q]
    for (int o = t; o < 9 * 3 * 49; o += 256) {
        int r = o / 147, rem = o % 147, c = rem / 49, q = rem % 49;
        float acc = 0.f;
        for (int m = 0; m < 64; m++) acc += wi2[m * 9 + r] * wi1[(m * 3 + c) * 49 + q];
        d_Wr[o] = acc;
    }
    if (t < 9) {
        float acc = 0.f;
        for (int m = 0; m < 64; m++) acc += wi2[m * 9 + t] * bi1[m];
        d_beta[t] = acc;
    }
    if (t == 0) {
        float acc = bi2[0];
        for (int m = 0; m < 64; m++) {
            float sw = 0.f;
            for (int r = 0; r < 9; r++) sw += wi2[m * 9 + r];
            acc += bi1[m] * sw;
        }
        d_bc = acc;
    }
}

// ---------------- k1b: border correction deltas ----------------
// True ini_img = composite - sum over conv2-taps landing outside the valid y1
// region of (beta[r] + sum_{c,q} Wr[r,c,q] * x_pad[...]).
__global__ void k1b_border(const float* __restrict__ x) {
    int gid = blockIdx.x * blockDim.x + threadIdx.x;
    if (gid >= 4 * 4 * 512) return;
    int b = gid / 2048, rem = gid % 2048, edge = rem / 512, idx = rem % 512;
    int oy, ox;
    if (edge == 0) { oy = 0;   ox = idx; }
    else if (edge == 1) { oy = 511; ox = idx; }
    else if (edge == 2) { oy = idx; ox = 0; }
    else { oy = idx; ox = 511; }
    const float* xb = x + (size_t)b * 3 * HW * HW;
    float delta = 0.f;
    for (int ry = 0; ry < 3; ry++)
        for (int rx = 0; rx < 3; rx++) {
            int py = oy + ry - 1, px = ox + rx - 1;
            if (py >= 0 && py < HW && px >= 0 && px < HW) continue;  // tap inside: no correction
            int r = ry * 3 + rx;
            float acc = d_beta[r];
            for (int c = 0; c < 3; c++)
                for (int qy = 0; qy < 7; qy++) {
                    int gy = py + qy - 3;
                    if (gy < 0 || gy >= HW) continue;
                    for (int qx = 0; qx < 7; qx++) {
                        int gx = px + qx - 3;
                        if (gx < 0 || gx >= HW) continue;
                        acc += d_Wr[(r * 3 + c) * 49 + qy * 7 + qx] * xb[c * HW * HW + gy * HW + gx];
                    }
                }
            delta += acc;
        }
    d_delta[b][edge][idx] = -delta;
}

// ---------------- k1: composed 9x9 conv + M-transform + relu -> u_img ----------------
// Block: 64 wide x 32 tall output region (4 patch-rows x 8 patch-cols). 256 threads.
__global__ void __launch_bounds__(256) k1_img(const float* __restrict__ x) {
    __shared__ float sxc[40 * 72];   // one channel of the input halo region
    __shared__ float swc[3 * 81];
    __shared__ float sM[64 * 65];
    __shared__ float sv[32 * 65];
    int t = threadIdx.x;
    int b = blockIdx.z, xg = blockIdx.x, yg = blockIdx.y;
    int ix0 = xg * 64, iy0 = yg * 32;
    const float* xb = x + (size_t)b * 3 * HW * HW;

    for (int i = t; i < 3 * 81; i += 256) swc[i] = d_wc[i];
    for (int i = t; i < 64 * 64; i += 256) sM[(i >> 6) * 65 + (i & 63)] = d_M[i];

    int col = t & 63, rg = t >> 6;
    float acc[8];
    float bias = d_bc;
#pragma unroll
    for (int j = 0; j < 8; j++) acc[j] = bias;

    for (int c = 0; c < 3; c++) {
        __syncthreads();
        for (int i = t; i < 2880; i += 256) {
            int r = i / 72, cc = i % 72;
            int gy = iy0 - 4 + r, gx = ix0 - 4 + cc;
            sxc[i] = (gy >= 0 && gy < HW && gx >= 0 && gx < HW) ? xb[c * HW * HW + gy * HW + gx] : 0.f;
        }
        __syncthreads();
#pragma unroll
        for (int dx = 0; dx < 9; dx++) {
            float win[16];
#pragma unroll
            for (int u = 0; u < 16; u++) win[u] = sxc[(rg * 8 + u) * 72 + col + dx];
#pragma unroll
            for (int dy = 0; dy < 9; dy++) {
                float w = swc[c * 81 + dy * 9 + dx];
#pragma unroll
                for (int j = 0; j < 8; j++) acc[j] += w * win[j + dy];
            }
        }
    }

    // border corrections, then stash v into smem laid out per-patch
    int oybase = iy0 + rg * 8;
    int ox = ix0 + col;
#pragma unroll
    for (int j = 0; j < 8; j++) {
        int oy = oybase + j;
        float a = acc[j];
        if (oy == 0) a += d_delta[b][0][ox];
        if (oy == 511) a += d_delta[b][1][ox];
        if (ox == 0 && oy > 0 && oy < 511) a += d_delta[b][2][oy];
        if (ox == 511 && oy > 0 && oy < 511) a += d_delta[b][3][oy];
        sv[(rg * 8 + (col >> 3)) * 65 + j * 8 + (col & 7)] = a;
    }
    __syncthreads();

    // u = relu(M v) for the 32 patches
    int i = t & 63, pb = t >> 6;
    float s[8];
#pragma unroll
    for (int kk = 0; kk < 8; kk++) s[kk] = 0.f;
    for (int j = 0; j < 64; j++) {
        float mv = sM[i * 65 + j];
#pragma unroll
        for (int kk = 0; kk < 8; kk++) s[kk] += mv * sv[(pb + 4 * kk) * 65 + j];
    }
    int prow0 = iy0 >> 3, pcol0 = ix0 >> 3;
#pragma unroll
    for (int kk = 0; kk < 8; kk++) {
        int p = pb + 4 * kk;
        int l = (prow0 + (p >> 3)) * 64 + pcol0 + (p & 7);
        d_uimg[((size_t)b * LPATCH + l) * 64 + i] = fmaxf(s[kk], 0.f);
    }
}

// ---------------- k2: 1x1 conv on fea (/4) + M-transform + relu -> u_fea ----------------
// Block: 128 wide x 8 tall region (one patch-row, 16 patches). 256 threads.
__global__ void __launch_bounds__(256) k2_fea(const float* __restrict__ fea,
                                              const float* __restrict__ wfea,
                                              const float* __restrict__ bfea) {
    __shared__ float sM[64 * 65];
    __shared__ float sv[16 * 65];
    __shared__ float swf[64];
    int t = threadIdx.x;
    int b = blockIdx.z, prow = blockIdx.y, xg = blockIdx.x;
    for (int i = t; i < 64 * 64; i += 256) sM[(i >> 6) * 65 + (i & 63)] = d_M[i];
    if (t < 64) swf[t] = wfea[t];
    __syncthreads();

    int r = t >> 5, c4 = t & 31;
    const float* fb = fea + (size_t)b * 64 * HW * HW + (size_t)(prow * 8 + r) * HW + xg * 128 + c4 * 4;
    float4 acc = {0.f, 0.f, 0.f, 0.f};
#pragma unroll 4
    for (int ch = 0; ch < 64; ch++) {
        float4 v = *(const float4*)(fb + (size_t)ch * HW * HW);
        float w = swf[ch];
        acc.x += w * v.x; acc.y += w * v.y; acc.z += w * v.z; acc.w += w * v.w;
    }
    float bias = bfea[0];
    int colbase = c4 * 4;
    float* svp = &sv[(colbase >> 3) * 65 + r * 8 + (colbase & 7)];
    svp[0] = (acc.x + bias) * 0.25f;
    svp[1] = (acc.y + bias) * 0.25f;
    svp[2] = (acc.z + bias) * 0.25f;
    svp[3] = (acc.w + bias) * 0.25f;
    __syncthreads();

    int i = t & 63, pb = t >> 6;
    float s[4] = {0.f, 0.f, 0.f, 0.f};
    for (int j = 0; j < 64; j++) {
        float mv = sM[i * 65 + j];
#pragma unroll
        for (int kk = 0; kk < 4; kk++) s[kk] += mv * sv[(pb + 4 * kk) * 65 + j];
    }
#pragma unroll
    for (int kk = 0; kk < 4; kk++) {
        int p = pb + 4 * kk;
        int l = prow * 64 + xg * 16 + p;
        d_ufea[((size_t)b * LPATCH + l) * 64 + i] = fmaxf(s[kk], 0.f);
    }
}

// ---------------- k3: batched gram GEMM, tf32 mma.sync with 3-pass correction ----------------
__device__ __forceinline__ unsigned f2tf(float x) {
    unsigned r;
    asm("cvt.rna.tf32.f32 %0, %1;" : "=r"(r) : "f"(x));
    return r;
}

#define MMA_TF32(d, a, bf)                                                                  \
    asm volatile(                                                                           \
        "mma.sync.aligned.m16n8k8.row.col.f32.tf32.tf32.f32 "                               \
        "{%0,%1,%2,%3},{%4,%5,%6,%7},{%8,%9},{%0,%1,%2,%3};"                                \
        : "+f"(d[0]), "+f"(d[1]), "+f"(d[2]), "+f"(d[3])                                    \
        : "r"(a[0]), "r"(a[1]), "r"(a[2]), "r"(a[3]), "r"(bf[0]), "r"(bf[1]))

__global__ void __launch_bounds__(256, 1) k3_gemm(float* __restrict__ att) {
    extern __shared__ float sm[];
    float* As = sm;                // [128][68]
    float* Bs = sm + 128 * 68;     // [128][68]
    int t = threadIdx.x;
    int bm = blockIdx.x, bn = blockIdx.y, b = blockIdx.z;
    const float* Ag = d_uimg + ((size_t)b * LPATCH + bm * 128) * 64;
    const float* Bg = d_ufea + ((size_t)b * LPATCH + bn * 128) * 64;
#pragma unroll
    for (int i = 0; i < 8; i++) {
        int idx = t + i * 256;  // float4 index over 128x16
        int m = idx >> 4, k4 = idx & 15;
        float4 av = *(const float4*)(Ag + m * 64 + k4 * 4);
        float4 bv = *(const float4*)(Bg + m * 64 + k4 * 4);
        *(float4*)(As + m * 68 + k4 * 4) = av;
        *(float4*)(Bs + m * 68 + k4 * 4) = bv;
    }
    __syncthreads();

    int warp = t >> 5, lane = t & 31;
    int g = lane >> 2, tig = lane & 3;
    int wm = (warp >> 2) * 64;
    int wn = (warp & 3) * 32;

    float acc[4][4][4];
#pragma unroll
    for (int mi = 0; mi < 4; mi++)
#pragma unroll
        for (int ni = 0; ni < 4; ni++)
#pragma unroll
            for (int q = 0; q < 4; q++) acc[mi][ni][q] = 0.f;

#pragma unroll
    for (int ks = 0; ks < 8; ks++) {
        int k0 = ks * 8;
        unsigned ahi[4][4], alo[4][4];
#pragma unroll
        for (int mi = 0; mi < 4; mi++) {
            int r0 = wm + mi * 16;
            float a0 = As[(r0 + g) * 68 + k0 + tig];
            float a1 = As[(r0 + g + 8) * 68 + k0 + tig];
            float a2 = As[(r0 + g) * 68 + k0 + tig + 4];
            float a3 = As[(r0 + g + 8) * 68 + k0 + tig + 4];
            ahi[mi][0] = f2tf(a0); alo[mi][0] = f2tf(a0 - __uint_as_float(ahi[mi][0]));
            ahi[mi][1] = f2tf(a1); alo[mi][1] = f2tf(a1 - __uint_as_float(ahi[mi][1]));
            ahi[mi][2] = f2tf(a2); alo[mi][2] = f2tf(a2 - __uint_as_float(ahi[mi][2]));
            ahi[mi][3] = f2tf(a3); alo[mi][3] = f2tf(a3 - __uint_as_float(ahi[mi][3]));
        }
        unsigned bhi[4][2], blo[4][2];
#pragma unroll
        for (int ni = 0; ni < 4; ni++) {
            int c0 = wn + ni * 8;
            float b0 = Bs[(c0 + g) * 68 + k0 + tig];
            float b1 = Bs[(c0 + g) * 68 + k0 + tig + 4];
            bhi[ni][0] = f2tf(b0); blo[ni][0] = f2tf(b0 - __uint_as_float(bhi[ni][0]));
            bhi[ni][1] = f2tf(b1); blo[ni][1] = f2tf(b1 - __uint_as_float(bhi[ni][1]));
        }
#pragma unroll
        for (int mi = 0; mi < 4; mi++)
#pragma unroll
            for (int ni = 0; ni < 4; ni++) {
                MMA_TF32(acc[mi][ni], ahi[mi], bhi[ni]);
                MMA_TF32(acc[mi][ni], alo[mi], bhi[ni]);
                MMA_TF32(acc[mi][ni], ahi[mi], blo[ni]);
            }
    }

    const float S = 1.f / 64.f;
    float* Cb = att + (size_t)b * LPATCH * LPATCH;
#pragma unroll
    for (int mi = 0; mi < 4; mi++)
#pragma unroll
        for (int ni = 0; ni < 4; ni++) {
            int row = bm * 128 + wm + mi * 16 + g;
            int colc = bn * 128 + wn + ni * 8 + tig * 2;
            float2 v0 = {acc[mi][ni][0] * S, acc[mi][ni][1] * S};
            float2 v1 = {acc[mi][ni][2] * S, acc[mi][ni][3] * S};
            *(float2*)(Cb + (size_t)row * LPATCH + colc) = v0;
            *(float2*)(Cb + (size_t)(row + 8) * LPATCH + colc) = v1;
        }
}

// ---------------- launch ----------------
extern "C" void kernel_launch(void* const* d_in, const int* in_sizes, int n_in,
                              void* d_out, int out_size) {
    const float* x    = (const float*)d_in[0];
    const float* fea  = (const float*)d_in[1];
    const float* wi1  = (const float*)d_in[2];
    const float* bi1  = (const float*)d_in[3];
    const float* wi2  = (const float*)d_in[4];
    const float* bi2  = (const float*)d_in[5];
    const float* wfea = (const float*)d_in[6];
    const float* bfea = (const float*)d_in[7];
    const float* w1   = (const float*)d_in[8];
    const float* w2   = (const float*)d_in[9];
    float* att = (float*)d_out;

    k0_compose<<<1, 256>>>(w1, w2, wi1, bi1, wi2, bi2);
    k1b_border<<<32, 256>>>(x);
    k1_img<<<dim3(8, 16, 4), 256>>>(x);
    k2_fea<<<dim3(4, 64, 4), 256>>>(fea, wfea, bfea);
    cudaFuncSetAttribute(k3_gemm, cudaFuncAttributeMaxDynamicSharedMemorySize, 2 * 128 * 68 * 4);
    k3_gemm<<<dim3(32, 32, 4), 256, 2 * 128 * 68 * 4>>>(att);
}

// round 2
// speedup vs baseline: 1.0802x; 1.0802x over previous
#include <cuda_runtime.h>
#include <cuda_bf16.h>
#include <cstdint>

#define HW 512
#define LPATCH 4096

// ---------------- scratch (static device globals; no allocation) ----------------
__device__ float d_M[64 * 64];        // composed linear  M = w2 @ w1
__device__ float d_wc[3 * 81];        // composed conv kernel [c][9][9]
__device__ float d_Wr[9 * 3 * 49];    // Wr[r][c][q] = sum_m w2[m,r]*w1[m,c,q]
__device__ float d_beta[9];           // beta[r] = sum_m w2[m,r]*b1[m]
__device__ float d_bc;                // composed bias
__device__ float d_delta[4][4][512];  // border corrections [b][edge][idx]
// u matrices stored as bf16 rows: [hi(64) | lo(64)] per patch, 256B/row
__device__ __align__(256) __nv_bfloat16 d_uimg[(size_t)4 * 4096 * 128];
__device__ __align__(256) __nv_bfloat16 d_ufea[(size_t)4 * 4096 * 128];

__device__ __forceinline__ void store_hilo(__nv_bfloat16* base, int i, float val) {
    __nv_bfloat16 hi = __float2bfloat16(val);
    float hif = __bfloat162float(hi);
    __nv_bfloat16 lo = __float2bfloat16(val - hif);
    base[i] = hi;
    base[64 + i] = lo;
}

// ---------------- k0: compose weights ----------------
__global__ void k0_compose(const float* __restrict__ w1l, const float* __restrict__ w2l,
                           const float* __restrict__ wi1, const float* __restrict__ bi1,
                           const float* __restrict__ wi2, const float* __restrict__ bi2) {
    int t = threadIdx.x;  // 256 threads, 1 block
    for (int o = t; o < 64 * 64; o += 256) {
        int i = o >> 6, j = o & 63;
        float s = 0.f;
        for (int k = 0; k < 128; k++) s += w2l[i * 128 + k] * w1l[k * 64 + j];
        d_M[o] = s;
    }
    for (int o = t; o < 3 * 81; o += 256) {
        int c = o / 81, s = o % 81, sy = s / 9, sx = s % 9;
        float acc = 0.f;
        for (int ry = 0; ry < 3; ry++)
            for (int rx = 0; rx < 3; rx++) {
                int qy = sy - ry, qx = sx - rx;
                if (qy < 0 || qy > 6 || qx < 0 || qx > 6) continue;
                for (int m = 0; m < 64; m++)
                    acc += wi2[m * 9 + ry * 3 + rx] * wi1[(m * 3 + c) * 49 + qy * 7 + qx];
            }
        d_wc[o] = acc;
    }
    for (int o = t; o < 9 * 3 * 49; o += 256) {
        int r = o / 147, rem = o % 147, c = rem / 49, q = rem % 49;
        float acc = 0.f;
        for (int m = 0; m < 64; m++) acc += wi2[m * 9 + r] * wi1[(m * 3 + c) * 49 + q];
        d_Wr[o] = acc;
    }
    if (t < 9) {
        float acc = 0.f;
        for (int m = 0; m < 64; m++) acc += wi2[m * 9 + t] * bi1[m];
        d_beta[t] = acc;
    }
    if (t == 0) {
        float acc = bi2[0];
        for (int m = 0; m < 64; m++) {
            float sw = 0.f;
            for (int r = 0; r < 9; r++) sw += wi2[m * 9 + r];
            acc += bi1[m] * sw;
        }
        d_bc = acc;
    }
}

// ---------------- k1b: border correction deltas ----------------
__global__ void k1b_border(const float* __restrict__ x) {
    int gid = blockIdx.x * blockDim.x + threadIdx.x;
    if (gid >= 4 * 4 * 512) return;
    int b = gid / 2048, rem = gid % 2048, edge = rem / 512, idx = rem % 512;
    int oy, ox;
    if (edge == 0) { oy = 0;   ox = idx; }
    else if (edge == 1) { oy = 511; ox = idx; }
    else if (edge == 2) { oy = idx; ox = 0; }
    else { oy = idx; ox = 511; }
    const float* xb = x + (size_t)b * 3 * HW * HW;
    float delta = 0.f;
    for (int ry = 0; ry < 3; ry++)
        for (int rx = 0; rx < 3; rx++) {
            int py = oy + ry - 1, px = ox + rx - 1;
            if (py >= 0 && py < HW && px >= 0 && px < HW) continue;
            int r = ry * 3 + rx;
            float acc = d_beta[r];
            for (int c = 0; c < 3; c++)
                for (int qy = 0; qy < 7; qy++) {
                    int gy = py + qy - 3;
                    if (gy < 0 || gy >= HW) continue;
                    for (int qx = 0; qx < 7; qx++) {
                        int gx = px + qx - 3;
                        if (gx < 0 || gx >= HW) continue;
                        acc += d_Wr[(r * 3 + c) * 49 + qy * 7 + qx] * xb[c * HW * HW + gy * HW + gx];
                    }
                }
            delta += acc;
        }
    d_delta[b][edge][idx] = -delta;
}

// ---------------- k1: composed 9x9 conv + M-transform + relu -> u_img ----------------
__global__ void __launch_bounds__(256) k1_img(const float* __restrict__ x) {
    __shared__ float sxc[40 * 72];
    __shared__ float swc[3 * 81];
    __shared__ float sM[64 * 65];
    __shared__ float sv[32 * 65];
    int t = threadIdx.x;
    int b = blockIdx.z, xg = blockIdx.x, yg = blockIdx.y;
    int ix0 = xg * 64, iy0 = yg * 32;
    const float* xb = x + (size_t)b * 3 * HW * HW;

    for (int i = t; i < 3 * 81; i += 256) swc[i] = d_wc[i];
    for (int i = t; i < 64 * 64; i += 256) sM[(i >> 6) * 65 + (i & 63)] = d_M[i];

    int col = t & 63, rg = t >> 6;
    float acc[8];
    float bias = d_bc;
#pragma unroll
    for (int j = 0; j < 8; j++) acc[j] = bias;

    for (int c = 0; c < 3; c++) {
        __syncthreads();
        for (int i = t; i < 2880; i += 256) {
            int r = i / 72, cc = i % 72;
            int gy = iy0 - 4 + r, gx = ix0 - 4 + cc;
            sxc[i] = (gy >= 0 && gy < HW && gx >= 0 && gx < HW) ? xb[c * HW * HW + gy * HW + gx] : 0.f;
        }
        __syncthreads();
#pragma unroll
        for (int dx = 0; dx < 9; dx++) {
            float win[16];
#pragma unroll
            for (int u = 0; u < 16; u++) win[u] = sxc[(rg * 8 + u) * 72 + col + dx];
#pragma unroll
            for (int dy = 0; dy < 9; dy++) {
                float w = swc[c * 81 + dy * 9 + dx];
#pragma unroll
                for (int j = 0; j < 8; j++) acc[j] += w * win[j + dy];
            }
        }
    }

    int oybase = iy0 + rg * 8;
    int ox = ix0 + col;
#pragma unroll
    for (int j = 0; j < 8; j++) {
        int oy = oybase + j;
        float a = acc[j];
        if (oy == 0) a += d_delta[b][0][ox];
        if (oy == 511) a += d_delta[b][1][ox];
        if (ox == 0 && oy > 0 && oy < 511) a += d_delta[b][2][oy];
        if (ox == 511 && oy > 0 && oy < 511) a += d_delta[b][3][oy];
        sv[(rg * 8 + (col >> 3)) * 65 + j * 8 + (col & 7)] = a;
    }
    __syncthreads();

    int i = t & 63, pb = t >> 6;
    float s[8];
#pragma unroll
    for (int kk = 0; kk < 8; kk++) s[kk] = 0.f;
    for (int j = 0; j < 64; j++) {
        float mv = sM[i * 65 + j];
#pragma unroll
        for (int kk = 0; kk < 8; kk++) s[kk] += mv * sv[(pb + 4 * kk) * 65 + j];
    }
    int prow0 = iy0 >> 3, pcol0 = ix0 >> 3;
#pragma unroll
    for (int kk = 0; kk < 8; kk++) {
        int p = pb + 4 * kk;
        int l = (prow0 + (p >> 3)) * 64 + pcol0 + (p & 7);
        store_hilo(d_uimg + ((size_t)b * LPATCH + l) * 128, i, fmaxf(s[kk], 0.f));
    }
}

// ---------------- k2: 1x1 conv on fea (/4) + M-transform + relu -> u_fea ----------------
__global__ void __launch_bounds__(256) k2_fea(const float* __restrict__ fea,
                                              const float* __restrict__ wfea,
                                              const float* __restrict__ bfea) {
    __shared__ float sM[64 * 65];
    __shared__ float sv[16 * 65];
    __shared__ float swf[64];
    int t = threadIdx.x;
    int b = blockIdx.z, prow = blockIdx.y, xg = blockIdx.x;
    for (int i = t; i < 64 * 64; i += 256) sM[(i >> 6) * 65 + (i & 63)] = d_M[i];
    if (t < 64) swf[t] = wfea[t];
    __syncthreads();

    int r = t >> 5, c4 = t & 31;
    const float* fb = fea + (size_t)b * 64 * HW * HW + (size_t)(prow * 8 + r) * HW + xg * 128 + c4 * 4;
    float4 acc = {0.f, 0.f, 0.f, 0.f};
    // explicit 8-wide load batching for MLP
#pragma unroll
    for (int ch0 = 0; ch0 < 64; ch0 += 8) {
        float4 v[8];
#pragma unroll
        for (int u = 0; u < 8; u++) v[u] = *(const float4*)(fb + (size_t)(ch0 + u) * HW * HW);
#pragma unroll
        for (int u = 0; u < 8; u++) {
            float w = swf[ch0 + u];
            acc.x += w * v[u].x; acc.y += w * v[u].y;
            acc.z += w * v[u].z; acc.w += w * v[u].w;
        }
    }
    float bias = bfea[0];
    int colbase = c4 * 4;
    float* svp = &sv[(colbase >> 3) * 65 + r * 8 + (colbase & 7)];
    svp[0] = (acc.x + bias) * 0.25f;
    svp[1] = (acc.y + bias) * 0.25f;
    svp[2] = (acc.z + bias) * 0.25f;
    svp[3] = (acc.w + bias) * 0.25f;
    __syncthreads();

    int i = t & 63, pb = t >> 6;
    float s[4] = {0.f, 0.f, 0.f, 0.f};
    for (int j = 0; j < 64; j++) {
        float mv = sM[i * 65 + j];
#pragma unroll
        for (int kk = 0; kk < 4; kk++) s[kk] += mv * sv[(pb + 4 * kk) * 65 + j];
    }
#pragma unroll
    for (int kk = 0; kk < 4; kk++) {
        int p = pb + 4 * kk;
        int l = prow * 64 + xg * 16 + p;
        store_hilo(d_ufea + ((size_t)b * LPATCH + l) * 128, i, fmaxf(s[kk], 0.f));
    }
}

// ---------------- k3: batched gram GEMM, bf16 m16n8k16 with 3-pass correction ----------------
#define MMA_BF16(d, a, bf)                                                                  \
    asm volatile(                                                                           \
        "mma.sync.aligned.m16n8k16.row.col.f32.bf16.bf16.f32 "                              \
        "{%0,%1,%2,%3},{%4,%5,%6,%7},{%8,%9},{%0,%1,%2,%3};"                                \
        : "+f"(d[0]), "+f"(d[1]), "+f"(d[2]), "+f"(d[3])                                    \
        : "r"(a[0]), "r"(a[1]), "r"(a[2]), "r"(a[3]), "r"(bf[0]), "r"(bf[1]))

// smem row stride: 68 32-bit words (136 bf16) -> 4r+col banks, conflict-free; 17 uint4/row
__global__ void __launch_bounds__(256, 1) k3_gemm(float* __restrict__ att) {
    extern __shared__ uint32_t sm32[];
    uint32_t* As = sm32;               // 128 rows x 68 words
    uint32_t* Bs = sm32 + 128 * 68;
    int t = threadIdx.x;
    int bm = blockIdx.x, bn = blockIdx.y, b = blockIdx.z;
    const uint4* Ag = (const uint4*)(d_uimg + ((size_t)b * LPATCH + bm * 128) * 128);
    const uint4* Bg = (const uint4*)(d_ufea + ((size_t)b * LPATCH + bn * 128) * 128);
#pragma unroll
    for (int i = 0; i < 8; i++) {
        int idx = t + i * 256;       // uint4 index over 128 rows x 16
        int m = idx >> 4, q = idx & 15;
        ((uint4*)As)[m * 17 + q] = Ag[m * 16 + q];
        ((uint4*)Bs)[m * 17 + q] = Bg[m * 16 + q];
    }
    __syncthreads();

    int warp = t >> 5, lane = t & 31;
    int g = lane >> 2, tig = lane & 3;
    int wm = (warp >> 2) * 64;
    int wn = (warp & 3) * 32;

    float acc[4][4][4];
#pragma unroll
    for (int mi = 0; mi < 4; mi++)
#pragma unroll
        for (int ni = 0; ni < 4; ni++)
#pragma unroll
            for (int q = 0; q < 4; q++) acc[mi][ni][q] = 0.f;

#pragma unroll
    for (int ks = 0; ks < 4; ks++) {
        int kb = ks * 8;  // word offset within hi segment (8 words = 16 bf16 per kstep)
        uint32_t ah[4][4], al[4][4];
#pragma unroll
        for (int mi = 0; mi < 4; mi++) {
            int r0 = wm + mi * 16;
            const uint32_t* p0 = As + (r0 + g) * 68 + kb + tig;
            const uint32_t* p1 = As + (r0 + g + 8) * 68 + kb + tig;
            ah[mi][0] = p0[0];  ah[mi][1] = p1[0];
            ah[mi][2] = p0[4];  ah[mi][3] = p1[4];
            al[mi][0] = p0[32]; al[mi][1] = p1[32];
            al[mi][2] = p0[36]; al[mi][3] = p1[36];
        }
        uint32_t bh[4][2], bl[4][2];
#pragma unroll
        for (int ni = 0; ni < 4; ni++) {
            int c0 = wn + ni * 8;
            const uint32_t* p = Bs + (c0 + g) * 68 + kb + tig;
            bh[ni][0] = p[0];  bh[ni][1] = p[4];
            bl[ni][0] = p[32]; bl[ni][1] = p[36];
        }
#pragma unroll
        for (int mi = 0; mi < 4; mi++)
#pragma unroll
            for (int ni = 0; ni < 4; ni++) {
                MMA_BF16(acc[mi][ni], ah[mi], bh[ni]);
                MMA_BF16(acc[mi][ni], ah[mi], bl[ni]);
                MMA_BF16(acc[mi][ni], al[mi], bh[ni]);
            }
    }

    const float S = 1.f / 64.f;
    float* Cb = att + (size_t)b * LPATCH * LPATCH;
#pragma unroll
    for (int mi = 0; mi < 4; mi++)
#pragma unroll
        for (int ni = 0; ni < 4; ni++) {
            int row = bm * 128 + wm + mi * 16 + g;
            int colc = bn * 128 + wn + ni * 8 + tig * 2;
            float2 v0 = {acc[mi][ni][0] * S, acc[mi][ni][1] * S};
            float2 v1 = {acc[mi][ni][2] * S, acc[mi][ni][3] * S};
            *(float2*)(Cb + (size_t)row * LPATCH + colc) = v0;
            *(float2*)(Cb + (size_t)(row + 8) * LPATCH + colc) = v1;
        }
}

// ---------------- launch ----------------
extern "C" void kernel_launch(void* const* d_in, const int* in_sizes, int n_in,
                              void* d_out, int out_size) {
    const float* x    = (const float*)d_in[0];
    const float* fea  = (const float*)d_in[1];
    const float* wi1  = (const float*)d_in[2];
    const float* bi1  = (const float*)d_in[3];
    const float* wi2  = (const float*)d_in[4];
    const float* bi2  = (const float*)d_in[5];
    const float* wfea = (const float*)d_in[6];
    const float* bfea = (const float*)d_in[7];
    const float* w1   = (const float*)d_in[8];
    const float* w2   = (const float*)d_in[9];
    float* att = (float*)d_out;

    k0_compose<<<1, 256>>>(w1, w2, wi1, bi1, wi2, bi2);
    k1b_border<<<32, 256>>>(x);
    k1_img<<<dim3(8, 16, 4), 256>>>(x);
    k2_fea<<<dim3(4, 64, 4), 256>>>(fea, wfea, bfea);
    cudaFuncSetAttribute(k3_gemm, cudaFuncAttributeMaxDynamicSharedMemorySize, 2 * 128 * 68 * 4);
    k3_gemm<<<dim3(32, 32, 4), 256, 2 * 128 * 68 * 4>>>(att);
}

// round 4
// speedup vs baseline: 1.2253x; 1.1344x over previous
#include <cuda_runtime.h>
#include <cuda_fp16.h>
#include <cstdint>

#define HW 512
#define LPATCH 4096

// ---------------- scratch (static device globals; no allocation) ----------------
__device__ float d_M[64 * 64];
__device__ float d_wc[3 * 81];
__device__ float d_Wr[9 * 3 * 49];
__device__ float d_beta[9];
__device__ float d_bc;
__device__ float d_delta[4][4][512];
// u matrices: fp16 rows [hi(64) | lo(64)], 256B/row, row-major
__device__ __align__(256) __half d_uimg[(size_t)4 * 4096 * 128];
__device__ __align__(256) __half d_ufea[(size_t)4 * 4096 * 128];

__device__ __forceinline__ void store_hilo(__half* base, int i, float val) {
    __half hi = __float2half_rn(val);
    float lo = val - __half2float(hi);
    base[i] = hi;
    base[64 + i] = __float2half_rn(lo);
}

// ---------------- k0: compose weights ----------------
__global__ void k0_compose(const float* __restrict__ w1l, const float* __restrict__ w2l,
                           const float* __restrict__ wi1, const float* __restrict__ bi1,
                           const float* __restrict__ wi2, const float* __restrict__ bi2) {
    int t = threadIdx.x;
    for (int o = t; o < 64 * 64; o += 256) {
        int i = o >> 6, j = o & 63;
        float s = 0.f;
        for (int k = 0; k < 128; k++) s += w2l[i * 128 + k] * w1l[k * 64 + j];
        d_M[o] = s;
    }
    for (int o = t; o < 3 * 81; o += 256) {
        int c = o / 81, s = o % 81, sy = s / 9, sx = s % 9;
        float acc = 0.f;
        for (int ry = 0; ry < 3; ry++)
            for (int rx = 0; rx < 3; rx++) {
                int qy = sy - ry, qx = sx - rx;
                if (qy < 0 || qy > 6 || qx < 0 || qx > 6) continue;
                for (int m = 0; m < 64; m++)
                    acc += wi2[m * 9 + ry * 3 + rx] * wi1[(m * 3 + c) * 49 + qy * 7 + qx];
            }
        d_wc[o] = acc;
    }
    for (int o = t; o < 9 * 3 * 49; o += 256) {
        int r = o / 147, rem = o % 147, c = rem / 49, q = rem % 49;
        float acc = 0.f;
        for (int m = 0; m < 64; m++) acc += wi2[m * 9 + r] * wi1[(m * 3 + c) * 49 + q];
        d_Wr[o] = acc;
    }
    if (t < 9) {
        float acc = 0.f;
        for (int m = 0; m < 64; m++) acc += wi2[m * 9 + t] * bi1[m];
        d_beta[t] = acc;
    }
    if (t == 0) {
        float acc = bi2[0];
        for (int m = 0; m < 64; m++) {
            float sw = 0.f;
            for (int r = 0; r < 9; r++) sw += wi2[m * 9 + r];
            acc += bi1[m] * sw;
        }
        d_bc = acc;
    }
}

// ---------------- k1b: border correction deltas ----------------
__global__ void k1b_border(const float* __restrict__ x) {
    int gid = blockIdx.x * blockDim.x + threadIdx.x;
    if (gid >= 4 * 4 * 512) return;
    int b = gid / 2048, rem = gid % 2048, edge = rem / 512, idx = rem % 512;
    int oy, ox;
    if (edge == 0) { oy = 0;   ox = idx; }
    else if (edge == 1) { oy = 511; ox = idx; }
    else if (edge == 2) { oy = idx; ox = 0; }
    else { oy = idx; ox = 511; }
    const float* xb = x + (size_t)b * 3 * HW * HW;
    float delta = 0.f;
    for (int ry = 0; ry < 3; ry++)
        for (int rx = 0; rx < 3; rx++) {
            int py = oy + ry - 1, px = ox + rx - 1;
            if (py >= 0 && py < HW && px >= 0 && px < HW) continue;
            int r = ry * 3 + rx;
            float acc = d_beta[r];
            for (int c = 0; c < 3; c++)
                for (int qy = 0; qy < 7; qy++) {
                    int gy = py + qy - 3;
                    if (gy < 0 || gy >= HW) continue;
                    for (int qx = 0; qx < 7; qx++) {
                        int gx = px + qx - 3;
                        if (gx < 0 || gx >= HW) continue;
                        acc += d_Wr[(r * 3 + c) * 49 + qy * 7 + qx] * xb[c * HW * HW + gy * HW + gx];
                    }
                }
            delta += acc;
        }
    d_delta[b][edge][idx] = -delta;
}

// ---------------- k1: composed 9x9 conv + M-transform + relu -> u_img ----------------
__global__ void __launch_bounds__(256) k1_img(const float* __restrict__ x) {
    __shared__ float sxc[40 * 72];
    __shared__ float swc[3 * 81];
    __shared__ float sM[64 * 65];
    __shared__ float sv[32 * 65];
    int t = threadIdx.x;
    int b = blockIdx.z, xg = blockIdx.x, yg = blockIdx.y;
    int ix0 = xg * 64, iy0 = yg * 32;
    const float* xb = x + (size_t)b * 3 * HW * HW;

    for (int i = t; i < 3 * 81; i += 256) swc[i] = d_wc[i];
    for (int i = t; i < 64 * 64; i += 256) sM[(i >> 6) * 65 + (i & 63)] = d_M[i];

    int col = t & 63, rg = t >> 6;
    float acc[8];
    float bias = d_bc;
#pragma unroll
    for (int j = 0; j < 8; j++) acc[j] = bias;

    for (int c = 0; c < 3; c++) {
        __syncthreads();
        for (int i = t; i < 2880; i += 256) {
            int r = i / 72, cc = i % 72;
            int gy = iy0 - 4 + r, gx = ix0 - 4 + cc;
            sxc[i] = (gy >= 0 && gy < HW && gx >= 0 && gx < HW) ? xb[c * HW * HW + gy * HW + gx] : 0.f;
        }
        __syncthreads();
#pragma unroll
        for (int dx = 0; dx < 9; dx++) {
            float win[16];
#pragma unroll
            for (int u = 0; u < 16; u++) win[u] = sxc[(rg * 8 + u) * 72 + col + dx];
#pragma unroll
            for (int dy = 0; dy < 9; dy++) {
                float w = swc[c * 81 + dy * 9 + dx];
#pragma unroll
                for (int j = 0; j < 8; j++) acc[j] += w * win[j + dy];
            }
        }
    }

    int oybase = iy0 + rg * 8;
    int ox = ix0 + col;
#pragma unroll
    for (int j = 0; j < 8; j++) {
        int oy = oybase + j;
        float a = acc[j];
        if (oy == 0) a += d_delta[b][0][ox];
        if (oy == 511) a += d_delta[b][1][ox];
        if (ox == 0 && oy > 0 && oy < 511) a += d_delta[b][2][oy];
        if (ox == 511 && oy > 0 && oy < 511) a += d_delta[b][3][oy];
        sv[(rg * 8 + (col >> 3)) * 65 + j * 8 + (col & 7)] = a;
    }
    __syncthreads();

    int i = t & 63, pb = t >> 6;
    float s[8];
#pragma unroll
    for (int kk = 0; kk < 8; kk++) s[kk] = 0.f;
    for (int j = 0; j < 64; j++) {
        float mv = sM[i * 65 + j];
#pragma unroll
        for (int kk = 0; kk < 8; kk++) s[kk] += mv * sv[(pb + 4 * kk) * 65 + j];
    }
    int prow0 = iy0 >> 3, pcol0 = ix0 >> 3;
#pragma unroll
    for (int kk = 0; kk < 8; kk++) {
        int p = pb + 4 * kk;
        int l = (prow0 + (p >> 3)) * 64 + pcol0 + (p & 7);
        store_hilo(d_uimg + ((size_t)b * LPATCH + l) * 128, i, fmaxf(s[kk], 0.f));
    }
}

// ---------------- k2: 1x1 conv on fea (/4) + M-transform + relu -> u_fea ----------------
__global__ void __launch_bounds__(256) k2_fea(const float* __restrict__ fea,
                                              const float* __restrict__ wfea,
                                              const float* __restrict__ bfea) {
    __shared__ float sM[64 * 65];
    __shared__ float sv[16 * 65];
    __shared__ float swf[64];
    int t = threadIdx.x;
    int b = blockIdx.z, prow = blockIdx.y, xg = blockIdx.x;
    for (int i = t; i < 64 * 64; i += 256) sM[(i >> 6) * 65 + (i & 63)] = d_M[i];
    if (t < 64) swf[t] = wfea[t];
    __syncthreads();

    int r = t >> 5, c4 = t & 31;
    const float* fb = fea + (size_t)b * 64 * HW * HW + (size_t)(prow * 8 + r) * HW + xg * 128 + c4 * 4;
    float4 acc = {0.f, 0.f, 0.f, 0.f};
    // 16-wide load batching: 16 outstanding LDG.128 per thread
#pragma unroll
    for (int ch0 = 0; ch0 < 64; ch0 += 16) {
        float4 v[16];
#pragma unroll
        for (int u = 0; u < 16; u++) v[u] = *(const float4*)(fb + (size_t)(ch0 + u) * HW * HW);
#pragma unroll
        for (int u = 0; u < 16; u++) {
            float w = swf[ch0 + u];
            acc.x += w * v[u].x; acc.y += w * v[u].y;
            acc.z += w * v[u].z; acc.w += w * v[u].w;
        }
    }
    float bias = bfea[0];
    int colbase = c4 * 4;
    float* svp = &sv[(colbase >> 3) * 65 + r * 8 + (colbase & 7)];
    svp[0] = (acc.x + bias) * 0.25f;
    svp[1] = (acc.y + bias) * 0.25f;
    svp[2] = (acc.z + bias) * 0.25f;
    svp[3] = (acc.w + bias) * 0.25f;
    __syncthreads();

    int i = t & 63, pb = t >> 6;
    float s[4] = {0.f, 0.f, 0.f, 0.f};
    for (int j = 0; j < 64; j++) {
        float mv = sM[i * 65 + j];
#pragma unroll
        for (int kk = 0; kk < 4; kk++) s[kk] += mv * sv[(pb + 4 * kk) * 65 + j];
    }
#pragma unroll
    for (int kk = 0; kk < 4; kk++) {
        int p = pb + 4 * kk;
        int l = prow * 64 + xg * 16 + p;
        store_hilo(d_ufea + ((size_t)b * LPATCH + l) * 128, i, fmaxf(s[kk], 0.f));
    }
}

// ================= k3: fp16 2-pass mma.sync GEMM with ldmatrix =================
__device__ __forceinline__ uint32_t cvta_smem(const void* p) {
    uint32_t a;
    asm("{ .reg .u64 t; cvta.to.shared.u64 t, %1; cvt.u32.u64 %0, t; }" : "=r"(a) : "l"(p));
    return a;
}
__device__ __forceinline__ void cp16(uint32_t dst, const void* src) {
    asm volatile("cp.async.cg.shared.global [%0], [%1], 16;" :: "r"(dst), "l"(src));
}

#define LDMX4(d, a)                                                                     \
    asm volatile("ldmatrix.sync.aligned.m8n8.x4.shared.b16 {%0,%1,%2,%3}, [%4];"        \
                 : "=r"((d)[0]), "=r"((d)[1]), "=r"((d)[2]), "=r"((d)[3]) : "r"(a))

#define MMA_F16(d, a, bf)                                                               \
    asm volatile(                                                                       \
        "mma.sync.aligned.m16n8k16.row.col.f32.f16.f16.f32 "                            \
        "{%0,%1,%2,%3},{%4,%5,%6,%7},{%8,%9},{%0,%1,%2,%3};"                            \
        : "+f"((d)[0]), "+f"((d)[1]), "+f"((d)[2]), "+f"((d)[3])                        \
        : "r"((a)[0]), "r"((a)[1]), "r"((a)[2]), "r"((a)[3]), "r"((bf)[0]), "r"((bf)[1]))

// smem: AH[128][72] | AL[128][72] | BH[128][72] fp16, 144B row stride
// 144B = 36 words == 4 (mod 32) -> 8-row ldmatrix groups land on disjoint 4-bank sets
#define ROWB 144
#define AH_OFF 0
#define AL_OFF (128 * ROWB)
#define BH_OFF (2 * 128 * ROWB)
#define K3_SMEM (3 * 128 * ROWB)

__global__ void __launch_bounds__(256, 2) k3_gemm(float* __restrict__ att) {
    extern __shared__ __align__(128) char dsm[];
    uint32_t sbase = cvta_smem(dsm);
    int t = threadIdx.x;
    int bm = blockIdx.x, bn = blockIdx.y, b = blockIdx.z;

    const char* Ag = (const char*)(d_uimg + ((size_t)b * LPATCH + bm * 128) * 128);
    const char* Bg = (const char*)(d_ufea + ((size_t)b * LPATCH + bn * 128) * 128);

#pragma unroll
    for (int i = 0; i < 12; i++) {
        int id = t + i * 256;
        if (id < 2048) {  // A: hi (c<8) and lo (c>=8)
            int row = id >> 4, c = id & 15;
            uint32_t dst = sbase + (c >> 3) * AL_OFF + row * ROWB + (c & 7) * 16;
            cp16(dst, Ag + row * 256 + c * 16);
        } else {          // B hi only
            int j = id - 2048;
            int row = j >> 3, c = j & 7;
            cp16(sbase + BH_OFF + row * ROWB + c * 16, Bg + row * 256 + c * 16);
        }
    }
    asm volatile("cp.async.commit_group;\ncp.async.wait_group 0;" ::: "memory");
    __syncthreads();

    int warp = t >> 5, lane = t & 31;
    int wm = (warp >> 2) * 64;     // 4x4 warp-tile: 64 rows x 32 cols per warp
    int wn = (warp & 3) * 32;
    int mat = lane >> 3, r = lane & 7;
    // A ldmatrix per-lane offsets: row += (mat&1)*8 + r ; col += (mat>>1)*8
    int a_row = (mat & 1) * 8 + r, a_col = (mat >> 1) * 8;
    // B ldmatrix per-lane offsets: row += (mat>>1)*8 + r ; col += (mat&1)*8
    int b_row = (mat >> 1) * 8 + r, b_col = (mat & 1) * 8;

    float acc[4][4][4];
#pragma unroll
    for (int mi = 0; mi < 4; mi++)
#pragma unroll
        for (int ni = 0; ni < 4; ni++)
#pragma unroll
            for (int q = 0; q < 4; q++) acc[mi][ni][q] = 0.f;

#pragma unroll
    for (int k = 0; k < 4; k++) {
        int k0 = k * 16;
        uint32_t bfr[4][2];
#pragma unroll
        for (int ni2 = 0; ni2 < 2; ni2++) {
            uint32_t tmp[4];
            uint32_t addr = sbase + BH_OFF + (wn + ni2 * 16 + b_row) * ROWB + (k0 + b_col) * 2;
            LDMX4(tmp, addr);
            bfr[ni2 * 2][0] = tmp[0]; bfr[ni2 * 2][1] = tmp[1];
            bfr[ni2 * 2 + 1][0] = tmp[2]; bfr[ni2 * 2 + 1][1] = tmp[3];
        }
        uint32_t afr[4][4];
#pragma unroll
        for (int mi = 0; mi < 4; mi++) {
            uint32_t addr = sbase + AH_OFF + (wm + mi * 16 + a_row) * ROWB + (k0 + a_col) * 2;
            LDMX4(afr[mi], addr);
        }
#pragma unroll
        for (int mi = 0; mi < 4; mi++)
#pragma unroll
            for (int ni = 0; ni < 4; ni++) MMA_F16(acc[mi][ni], afr[mi], bfr[ni]);
#pragma unroll
        for (int mi = 0; mi < 4; mi++) {
            uint32_t addr = sbase + AL_OFF + (wm + mi * 16 + a_row) * ROWB + (k0 + a_col) * 2;
            LDMX4(afr[mi], addr);
        }
#pragma unroll
        for (int mi = 0; mi < 4; mi++)
#pragma unroll
            for (int ni = 0; ni < 4; ni++) MMA_F16(acc[mi][ni], afr[mi], bfr[ni]);
    }

    const float S = 1.f / 64.f;
    int g = lane >> 2, tig = lane & 3;
    float* Cb = att + (size_t)b * LPATCH * LPATCH;
#pragma unroll
    for (int mi = 0; mi < 4; mi++)
#pragma unroll
        for (int ni = 0; ni < 4; ni++) {
            int row = bm * 128 + wm + mi * 16 + g;
            int colc = bn * 128 + wn + ni * 8 + tig * 2;
            float2 v0 = {acc[mi][ni][0] * S, acc[mi][ni][1] * S};
            float2 v1 = {acc[mi][ni][2] * S, acc[mi][ni][3] * S};
            *(float2*)(Cb + (size_t)row * LPATCH + colc) = v0;
            *(float2*)(Cb + (size_t)(row + 8) * LPATCH + colc) = v1;
        }
}

// ---------------- launch ----------------
extern "C" void kernel_launch(void* const* d_in, const int* in_sizes, int n_in,
                              void* d_out, int out_size) {
    const float* x    = (const float*)d_in[0];
    const float* fea  = (const float*)d_in[1];
    const float* wi1  = (const float*)d_in[2];
    const float* bi1  = (const float*)d_in[3];
    const float* wi2  = (const float*)d_in[4];
    const float* bi2  = (const float*)d_in[5];
    const float* wfea = (const float*)d_in[6];
    const float* bfea = (const float*)d_in[7];
    const float* w1   = (const float*)d_in[8];
    const float* w2   = (const float*)d_in[9];
    float* att = (float*)d_out;

    k0_compose<<<1, 256>>>(w1, w2, wi1, bi1, wi2, bi2);
    k1b_border<<<32, 256>>>(x);
    k1_img<<<dim3(8, 16, 4), 256>>>(x);
    k2_fea<<<dim3(4, 64, 4), 256>>>(fea, wfea, bfea);
    cudaFuncSetAttribute(k3_gemm, cudaFuncAttributeMaxDynamicSharedMemorySize, K3_SMEM);
    k3_gemm<<<dim3(32, 32, 4), 256, K3_SMEM>>>(att);
}

// round 5
// speedup vs baseline: 1.3198x; 1.0770x over previous
#include <cuda_runtime.h>
#include <cuda_fp16.h>
#include <cstdint>

#define HW 512
#define LPATCH 4096

// ---------------- scratch (static device globals; no allocation) ----------------
__device__ float d_M[64 * 64];
__device__ float d_wc[3 * 81];
__device__ float d_Wr[9 * 3 * 49];
__device__ float d_beta[9];
__device__ float d_bc;
__device__ float d_delta[4][4][512];
// u matrices: fp16, 64 per row (128B rows)
__device__ __align__(256) __half d_uimg[(size_t)4 * 4096 * 64];
__device__ __align__(256) __half d_ufea[(size_t)4 * 4096 * 64];

// ---------------- k0: compose weights ----------------
__global__ void k0_compose(const float* __restrict__ w1l, const float* __restrict__ w2l,
                           const float* __restrict__ wi1, const float* __restrict__ bi1,
                           const float* __restrict__ wi2, const float* __restrict__ bi2) {
    int t = threadIdx.x;
    for (int o = t; o < 64 * 64; o += 256) {
        int i = o >> 6, j = o & 63;
        float s = 0.f;
        for (int k = 0; k < 128; k++) s += w2l[i * 128 + k] * w1l[k * 64 + j];
        d_M[o] = s;
    }
    for (int o = t; o < 3 * 81; o += 256) {
        int c = o / 81, s = o % 81, sy = s / 9, sx = s % 9;
        float acc = 0.f;
        for (int ry = 0; ry < 3; ry++)
            for (int rx = 0; rx < 3; rx++) {
                int qy = sy - ry, qx = sx - rx;
                if (qy < 0 || qy > 6 || qx < 0 || qx > 6) continue;
                for (int m = 0; m < 64; m++)
                    acc += wi2[m * 9 + ry * 3 + rx] * wi1[(m * 3 + c) * 49 + qy * 7 + qx];
            }
        d_wc[o] = acc;
    }
    for (int o = t; o < 9 * 3 * 49; o += 256) {
        int r = o / 147, rem = o % 147, c = rem / 49, q = rem % 49;
        float acc = 0.f;
        for (int m = 0; m < 64; m++) acc += wi2[m * 9 + r] * wi1[(m * 3 + c) * 49 + q];
        d_Wr[o] = acc;
    }
    if (t < 9) {
        float acc = 0.f;
        for (int m = 0; m < 64; m++) acc += wi2[m * 9 + t] * bi1[m];
        d_beta[t] = acc;
    }
    if (t == 0) {
        float acc = bi2[0];
        for (int m = 0; m < 64; m++) {
            float sw = 0.f;
            for (int r = 0; r < 9; r++) sw += wi2[m * 9 + r];
            acc += bi1[m] * sw;
        }
        d_bc = acc;
    }
}

// ---------------- k1b: border correction deltas ----------------
__global__ void k1b_border(const float* __restrict__ x) {
    int gid = blockIdx.x * blockDim.x + threadIdx.x;
    if (gid >= 4 * 4 * 512) return;
    int b = gid / 2048, rem = gid % 2048, edge = rem / 512, idx = rem % 512;
    int oy, ox;
    if (edge == 0) { oy = 0;   ox = idx; }
    else if (edge == 1) { oy = 511; ox = idx; }
    else if (edge == 2) { oy = idx; ox = 0; }
    else { oy = idx; ox = 511; }
    const float* xb = x + (size_t)b * 3 * HW * HW;
    float delta = 0.f;
    for (int ry = 0; ry < 3; ry++)
        for (int rx = 0; rx < 3; rx++) {
            int py = oy + ry - 1, px = ox + rx - 1;
            if (py >= 0 && py < HW && px >= 0 && px < HW) continue;
            int r = ry * 3 + rx;
            float acc = d_beta[r];
            for (int c = 0; c < 3; c++)
                for (int qy = 0; qy < 7; qy++) {
                    int gy = py + qy - 3;
                    if (gy < 0 || gy >= HW) continue;
                    for (int qx = 0; qx < 7; qx++) {
                        int gx = px + qx - 3;
                        if (gx < 0 || gx >= HW) continue;
                        acc += d_Wr[(r * 3 + c) * 49 + qy * 7 + qx] * xb[c * HW * HW + gy * HW + gx];
                    }
                }
            delta += acc;
        }
    d_delta[b][edge][idx] = -delta;
}

// ---------------- k1: composed 9x9 conv + M-transform + relu -> u_img ----------------
__global__ void __launch_bounds__(256) k1_img(const float* __restrict__ x) {
    __shared__ float sxc[40 * 72];
    __shared__ float swc[3 * 81];
    __shared__ float sM[64 * 65];
    __shared__ float sv[32 * 65];
    int t = threadIdx.x;
    int b = blockIdx.z, xg = blockIdx.x, yg = blockIdx.y;
    int ix0 = xg * 64, iy0 = yg * 32;
    const float* xb = x + (size_t)b * 3 * HW * HW;

    for (int i = t; i < 3 * 81; i += 256) swc[i] = d_wc[i];
    for (int i = t; i < 64 * 64; i += 256) sM[(i >> 6) * 65 + (i & 63)] = d_M[i];

    int col = t & 63, rg = t >> 6;
    float acc[8];
    float bias = d_bc;
#pragma unroll
    for (int j = 0; j < 8; j++) acc[j] = bias;

    for (int c = 0; c < 3; c++) {
        __syncthreads();
        for (int i = t; i < 2880; i += 256) {
            int r = i / 72, cc = i % 72;
            int gy = iy0 - 4 + r, gx = ix0 - 4 + cc;
            sxc[i] = (gy >= 0 && gy < HW && gx >= 0 && gx < HW) ? xb[c * HW * HW + gy * HW + gx] : 0.f;
        }
        __syncthreads();
#pragma unroll
        for (int dx = 0; dx < 9; dx++) {
            float win[16];
#pragma unroll
            for (int u = 0; u < 16; u++) win[u] = sxc[(rg * 8 + u) * 72 + col + dx];
#pragma unroll
            for (int dy = 0; dy < 9; dy++) {
                float w = swc[c * 81 + dy * 9 + dx];
#pragma unroll
                for (int j = 0; j < 8; j++) acc[j] += w * win[j + dy];
            }
        }
    }

    int oybase = iy0 + rg * 8;
    int ox = ix0 + col;
#pragma unroll
    for (int j = 0; j < 8; j++) {
        int oy = oybase + j;
        float a = acc[j];
        if (oy == 0) a += d_delta[b][0][ox];
        if (oy == 511) a += d_delta[b][1][ox];
        if (ox == 0 && oy > 0 && oy < 511) a += d_delta[b][2][oy];
        if (ox == 511 && oy > 0 && oy < 511) a += d_delta[b][3][oy];
        sv[(rg * 8 + (col >> 3)) * 65 + j * 8 + (col & 7)] = a;
    }
    __syncthreads();

    int i = t & 63, pb = t >> 6;
    float s[8];
#pragma unroll
    for (int kk = 0; kk < 8; kk++) s[kk] = 0.f;
    for (int j = 0; j < 64; j++) {
        float mv = sM[i * 65 + j];
#pragma unroll
        for (int kk = 0; kk < 8; kk++) s[kk] += mv * sv[(pb + 4 * kk) * 65 + j];
    }
    int prow0 = iy0 >> 3, pcol0 = ix0 >> 3;
#pragma unroll
    for (int kk = 0; kk < 8; kk++) {
        int p = pb + 4 * kk;
        int l = (prow0 + (p >> 3)) * 64 + pcol0 + (p & 7);
        d_uimg[((size_t)b * LPATCH + l) * 64 + i] = __float2half_rn(fmaxf(s[kk], 0.f));
    }
}

// ---------------- k2: 1x1 conv via cp.async smem staging ----------------
__device__ __forceinline__ uint32_t cvta_smem(const void* p) {
    uint32_t a;
    asm("{ .reg .u64 t; cvta.to.shared.u64 t, %1; cvt.u32.u64 %0, t; }" : "=r"(a) : "l"(p));
    return a;
}
__device__ __forceinline__ void cp16(uint32_t dst, const void* src) {
    asm volatile("cp.async.cg.shared.global [%0], [%1], 16;" :: "r"(dst), "l"(src));
}

__global__ void __launch_bounds__(256) k2_fea(const float* __restrict__ fea,
                                              const float* __restrict__ wfea,
                                              const float* __restrict__ bfea) {
    extern __shared__ __align__(16) float buf[];  // 2 stages x 8 ch x (8x128) floats
    __shared__ float sM[64 * 65];
    __shared__ float sv[16 * 65];
    __shared__ float swf[64];
    int t = threadIdx.x;
    int b = blockIdx.z, prow = blockIdx.y, xg = blockIdx.x;
    for (int i = t; i < 64 * 64; i += 256) sM[(i >> 6) * 65 + (i & 63)] = d_M[i];
    if (t < 64) swf[t] = wfea[t];

    const char* gbase = (const char*)(fea + (size_t)b * 64 * HW * HW + (size_t)(prow * 8) * HW + xg * 128);
    uint32_t sbuf = cvta_smem(buf);
    // per-thread load slot: 8 cp16 per chunk
    int lrow = (t >> 5) & 7, lc = t & 31, lch = t >> 8;  // t<256 so base ch from i
    (void)lch;

    // prologue: chunk 0 -> stage 0
#pragma unroll
    for (int i = 0; i < 8; i++) {
        int id = t + i * 256;               // 0..2047
        int ch = id >> 8, j = id & 255;     // ch 0..7
        int row = j >> 5, c = j & 31;
        cp16(sbuf + (ch * 1024 + row * 128 + c * 4) * 4,
             gbase + (size_t)ch * HW * HW * 4 + row * HW * 4 + c * 16);
    }
    asm volatile("cp.async.commit_group;" ::: "memory");

    int r = t >> 5, c4 = t & 31;
    float4 acc = {0.f, 0.f, 0.f, 0.f};

    for (int chunk = 0; chunk < 8; chunk++) {
        int st = chunk & 1;
        if (chunk + 1 < 8) {
            int nst = (chunk + 1) & 1;
            int ch0 = (chunk + 1) * 8;
#pragma unroll
            for (int i = 0; i < 8; i++) {
                int id = t + i * 256;
                int ch = id >> 8, j = id & 255;
                int row = j >> 5, c = j & 31;
                cp16(sbuf + (nst * 8192 + ch * 1024 + row * 128 + c * 4) * 4,
                     gbase + (size_t)(ch0 + ch) * HW * HW * 4 + row * HW * 4 + c * 16);
            }
            asm volatile("cp.async.commit_group;" ::: "memory");
            asm volatile("cp.async.wait_group 1;" ::: "memory");
        } else {
            asm volatile("cp.async.wait_group 0;" ::: "memory");
        }
        __syncthreads();
        const float* s = buf + st * 8192;
#pragma unroll
        for (int ch = 0; ch < 8; ch++) {
            float4 v = *(const float4*)(s + ch * 1024 + r * 128 + c4 * 4);
            float w = swf[chunk * 8 + ch];
            acc.x += w * v.x; acc.y += w * v.y;
            acc.z += w * v.z; acc.w += w * v.w;
        }
        __syncthreads();
    }

    float bias = bfea[0];
    int colbase = c4 * 4;
    float* svp = &sv[(colbase >> 3) * 65 + r * 8 + (colbase & 7)];
    svp[0] = (acc.x + bias) * 0.25f;
    svp[1] = (acc.y + bias) * 0.25f;
    svp[2] = (acc.z + bias) * 0.25f;
    svp[3] = (acc.w + bias) * 0.25f;
    __syncthreads();

    int i = t & 63, pb = t >> 6;
    float s2[4] = {0.f, 0.f, 0.f, 0.f};
    for (int j = 0; j < 64; j++) {
        float mv = sM[i * 65 + j];
#pragma unroll
        for (int kk = 0; kk < 4; kk++) s2[kk] += mv * sv[(pb + 4 * kk) * 65 + j];
    }
#pragma unroll
    for (int kk = 0; kk < 4; kk++) {
        int p = pb + 4 * kk;
        int l = prow * 64 + xg * 16 + p;
        d_ufea[((size_t)b * LPATCH + l) * 64 + i] = __float2half_rn(fmaxf(s2[kk], 0.f));
    }
}

// ================= k3: fp16 single-pass mma.sync GEMM with ldmatrix =================
#define LDMX4(d, a)                                                                     \
    asm volatile("ldmatrix.sync.aligned.m8n8.x4.shared.b16 {%0,%1,%2,%3}, [%4];"        \
                 : "=r"((d)[0]), "=r"((d)[1]), "=r"((d)[2]), "=r"((d)[3]) : "r"(a))

#define MMA_F16(d, a, bf)                                                               \
    asm volatile(                                                                       \
        "mma.sync.aligned.m16n8k16.row.col.f32.f16.f16.f32 "                            \
        "{%0,%1,%2,%3},{%4,%5,%6,%7},{%8,%9},{%0,%1,%2,%3};"                            \
        : "+f"((d)[0]), "+f"((d)[1]), "+f"((d)[2]), "+f"((d)[3])                        \
        : "r"((a)[0]), "r"((a)[1]), "r"((a)[2]), "r"((a)[3]), "r"((bf)[0]), "r"((bf)[1]))

// smem: A[128][72] | B[128][72] fp16, 144B row stride (36 words == 4 mod 32: conflict-free)
#define ROWB 144
#define B_OFF (128 * ROWB)
#define K3_SMEM (2 * 128 * ROWB)

__global__ void __launch_bounds__(256, 2) k3_gemm(float* __restrict__ att) {
    extern __shared__ __align__(128) char dsm[];
    uint32_t sbase = cvta_smem(dsm);
    int t = threadIdx.x;
    int bm = blockIdx.x, bn = blockIdx.y, b = blockIdx.z;

    const char* Ag = (const char*)(d_uimg + ((size_t)b * LPATCH + bm * 128) * 64);
    const char* Bg = (const char*)(d_ufea + ((size_t)b * LPATCH + bn * 128) * 64);

#pragma unroll
    for (int i = 0; i < 8; i++) {
        int id = t + i * 256;             // 0..2047 16B chunks
        int tile = id >> 10, j = id & 1023;
        int row = j >> 3, c = j & 7;
        cp16(sbase + tile * B_OFF + row * ROWB + c * 16,
             (tile ? Bg : Ag) + row * 128 + c * 16);
    }
    asm volatile("cp.async.commit_group;\ncp.async.wait_group 0;" ::: "memory");
    __syncthreads();

    int warp = t >> 5, lane = t & 31;
    int wm = (warp >> 2) * 64;
    int wn = (warp & 3) * 32;
    int mat = lane >> 3, r = lane & 7;
    int a_row = (mat & 1) * 8 + r, a_col = (mat >> 1) * 8;
    int b_row = (mat >> 1) * 8 + r, b_col = (mat & 1) * 8;

    float acc[4][4][4];
#pragma unroll
    for (int mi = 0; mi < 4; mi++)
#pragma unroll
        for (int ni = 0; ni < 4; ni++)
#pragma unroll
            for (int q = 0; q < 4; q++) acc[mi][ni][q] = 0.f;

#pragma unroll
    for (int k = 0; k < 4; k++) {
        int k0 = k * 16;
        uint32_t bfr[4][2];
#pragma unroll
        for (int ni2 = 0; ni2 < 2; ni2++) {
            uint32_t tmp[4];
            uint32_t addr = sbase + B_OFF + (wn + ni2 * 16 + b_row) * ROWB + (k0 + b_col) * 2;
            LDMX4(tmp, addr);
            bfr[ni2 * 2][0] = tmp[0]; bfr[ni2 * 2][1] = tmp[1];
            bfr[ni2 * 2 + 1][0] = tmp[2]; bfr[ni2 * 2 + 1][1] = tmp[3];
        }
        uint32_t afr[4][4];
#pragma unroll
        for (int mi = 0; mi < 4; mi++) {
            uint32_t addr = sbase + (wm + mi * 16 + a_row) * ROWB + (k0 + a_col) * 2;
            LDMX4(afr[mi], addr);
        }
#pragma unroll
        for (int mi = 0; mi < 4; mi++)
#pragma unroll
            for (int ni = 0; ni < 4; ni++) MMA_F16(acc[mi][ni], afr[mi], bfr[ni]);
    }

    const float S = 1.f / 64.f;
    int g = lane >> 2, tig = lane & 3;
    float* Cb = att + (size_t)b * LPATCH * LPATCH;
#pragma unroll
    for (int mi = 0; mi < 4; mi++)
#pragma unroll
        for (int ni = 0; ni < 4; ni++) {
            int row = bm * 128 + wm + mi * 16 + g;
            int colc = bn * 128 + wn + ni * 8 + tig * 2;
            float2 v0 = {acc[mi][ni][0] * S, acc[mi][ni][1] * S};
            float2 v1 = {acc[mi][ni][2] * S, acc[mi][ni][3] * S};
            *(float2*)(Cb + (size_t)row * LPATCH + colc) = v0;
            *(float2*)(Cb + (size_t)(row + 8) * LPATCH + colc) = v1;
        }
}

// ---------------- launch ----------------
extern "C" void kernel_launch(void* const* d_in, const int* in_sizes, int n_in,
                              void* d_out, int out_size) {
    const float* x    = (const float*)d_in[0];
    const float* fea  = (const float*)d_in[1];
    const float* wi1  = (const float*)d_in[2];
    const float* bi1  = (const float*)d_in[3];
    const float* wi2  = (const float*)d_in[4];
    const float* bi2  = (const float*)d_in[5];
    const float* wfea = (const float*)d_in[6];
    const float* bfea = (const float*)d_in[7];
    const float* w1   = (const float*)d_in[8];
    const float* w2   = (const float*)d_in[9];
    float* att = (float*)d_out;

    k0_compose<<<1, 256>>>(w1, w2, wi1, bi1, wi2, bi2);
    k1b_border<<<32, 256>>>(x);
    k1_img<<<dim3(8, 16, 4), 256>>>(x);
    cudaFuncSetAttribute(k2_fea, cudaFuncAttributeMaxDynamicSharedMemorySize, 65536);
    k2_fea<<<dim3(4, 64, 4), 256, 65536>>>(fea, wfea, bfea);
    cudaFuncSetAttribute(k3_gemm, cudaFuncAttributeMaxDynamicSharedMemorySize, K3_SMEM);
    k3_gemm<<<dim3(32, 32, 4), 256, K3_SMEM>>>(att);
}